// round 5
// baseline (speedup 1.0000x reference)
#include <cuda_runtime.h>
#include <cuda_bf16.h>
#include <mma.h>
#include <cstdint>
#include <cstddef>

using namespace nvcuda;

// Shapes: x[8,256,128,128] f32, kpts[8,4096,2], W[128,256], b[128] -> out[8,4096,128] f32
#define NB 8
#define NC 256
#define NPIX 16384            // 128*128
#define NE 128
#define NPTS 4096
#define NTILES 1024           // NB * NPIX/128
#define GRID1 148

// SMEM geometry (elements)
#define WLD 264               // W row stride: 256 + 8 pad (bf16)
#define XLD 136               // X row stride: 128 + 8 pad (bf16)
#define SM_WH_OFF 0
#define SM_WL_OFF (128 * WLD * 2)                 // 67584 B
#define SM_XH_OFF (2 * 128 * WLD * 2)             // 135168 B
#define SM_XL_OFF (SM_XH_OFF + 128 * XLD * 2)     // +34816
#define SM_TOT    (SM_XL_OFF + 128 * XLD * 2)     // 204800 B

// Scratch: Wx[b, pixel, e] fp32 (64 MiB)
__device__ float g_wx[(size_t)NB * NPIX * NE];

static __device__ __forceinline__ void split_pack(float a, float b, uint32_t& hp, uint32_t& lp) {
    __nv_bfloat16 h0 = __float2bfloat16_rn(a), h1 = __float2bfloat16_rn(b);
    float r0 = a - __bfloat162float(h0), r1 = b - __bfloat162float(h1);
    __nv_bfloat16 l0 = __float2bfloat16_rn(r0), l1 = __float2bfloat16_rn(r1);
    hp = (uint32_t)__bfloat16_as_ushort(h0) | ((uint32_t)__bfloat16_as_ushort(h1) << 16);
    lp = (uint32_t)__bfloat16_as_ushort(l0) | ((uint32_t)__bfloat16_as_ushort(l1) << 16);
}

// ===== Kernel 1: Wx[b,pix,e] = sum_c W[e,c] * x[b,c,pix]  (3x bf16-split WMMA) =====
__global__ void __launch_bounds__(256, 1) k1_whiten(const float* __restrict__ x,
                                                    const float* __restrict__ wmat) {
    extern __shared__ char smem[];
    __nv_bfloat16* Wh = (__nv_bfloat16*)(smem + SM_WH_OFF);
    __nv_bfloat16* Wl = (__nv_bfloat16*)(smem + SM_WL_OFF);
    __nv_bfloat16* Xh = (__nv_bfloat16*)(smem + SM_XH_OFF);
    __nv_bfloat16* Xl = (__nv_bfloat16*)(smem + SM_XL_OFF);

    const int tid = threadIdx.x;
    const int wid = tid >> 5;
    const int wm = wid & 3;          // 0..3 -> pixel sub-tile (32 rows)
    const int wn = wid >> 2;         // 0..1 -> E sub-tile (64 cols)

    // ---- W prologue: [128 E][256 c] -> hi/lo bf16 tiles, row stride WLD ----
    for (int q = tid; q < 16384; q += 256) {      // q: e = q>>7, c-pair = q&127
        int e = q >> 7, c2 = q & 127;
        float2 v = *(const float2*)(wmat + e * 256 + c2 * 2);
        uint32_t hp, lp; split_pack(v.x, v.y, hp, lp);
        *(uint32_t*)(Wh + e * WLD + c2 * 2) = hp;
        *(uint32_t*)(Wl + e * WLD + c2 * 2) = lp;
    }
    __syncthreads();

    const int pix_t = tid & 127;     // loader: pixel lane
    const int half  = tid >> 7;      // loader: k half (0/1)

    for (int T = blockIdx.x; T < NTILES; T += GRID1) {
        const int b = T >> 7;
        const int pix0 = (T & 127) << 7;
        const float* xb = x + (size_t)b * NC * NPIX + pix0;

        wmma::fragment<wmma::accumulator, 16, 16, 16, float> acc[2][4];
#pragma unroll
        for (int mi = 0; mi < 2; mi++)
#pragma unroll
            for (int ni = 0; ni < 4; ni++)
                wmma::fill_fragment(acc[mi][ni], 0.0f);

        for (int chunk = 0; chunk < 2; chunk++) {
            __syncthreads();   // previous chunk's MMAs done before overwrite
            // load 128 channels x 128 pixels, split, store to Xh/Xl
#pragma unroll 8
            for (int j = 0; j < 32; j++) {
                int ch = half * 64 + j * 2;       // within chunk
                int cg = chunk * 128 + ch;        // global channel
                float va = xb[(size_t)cg * NPIX + pix_t];
                float vb = xb[(size_t)(cg + 1) * NPIX + pix_t];
                uint32_t hp, lp; split_pack(va, vb, hp, lp);
                *(uint32_t*)(Xh + pix_t * XLD + ch) = hp;
                *(uint32_t*)(Xl + pix_t * XLD + ch) = lp;
            }
            __syncthreads();

#pragma unroll
            for (int ks = 0; ks < 8; ks++) {
                const int kb = ks * 16;
                const int kg = chunk * 128 + kb;
                wmma::fragment<wmma::matrix_a, 16, 16, 16, __nv_bfloat16, wmma::row_major> ah[2], al[2];
#pragma unroll
                for (int mi = 0; mi < 2; mi++) {
                    int prow = wm * 32 + mi * 16;
                    wmma::load_matrix_sync(ah[mi], Xh + prow * XLD + kb, XLD);
                    wmma::load_matrix_sync(al[mi], Xl + prow * XLD + kb, XLD);
                }
#pragma unroll
                for (int ni = 0; ni < 4; ni++) {
                    int erow = wn * 64 + ni * 16;
                    wmma::fragment<wmma::matrix_b, 16, 16, 16, __nv_bfloat16, wmma::col_major> bh, bl;
                    wmma::load_matrix_sync(bh, Wh + erow * WLD + kg, WLD);
                    wmma::load_matrix_sync(bl, Wl + erow * WLD + kg, WLD);
#pragma unroll
                    for (int mi = 0; mi < 2; mi++) {
                        wmma::mma_sync(acc[mi][ni], ah[mi], bh, acc[mi][ni]);
                        wmma::mma_sync(acc[mi][ni], al[mi], bh, acc[mi][ni]);
                        wmma::mma_sync(acc[mi][ni], ah[mi], bl, acc[mi][ni]);
                    }
                }
            }
        }

        // ---- epilogue: acc -> g_wx[b, pix, e] (E-contiguous) ----
        float* gp = g_wx + ((size_t)(b * NPIX + pix0)) * NE;
#pragma unroll
        for (int mi = 0; mi < 2; mi++)
#pragma unroll
            for (int ni = 0; ni < 4; ni++)
                wmma::store_matrix_sync(gp + (size_t)(wm * 32 + mi * 16) * NE + wn * 64 + ni * 16,
                                        acc[mi][ni], NE, wmma::mem_row_major);
        __syncthreads();
    }
}

// ===== Kernel 2: bilinear gather on Wx + bias + L2-normalize =====
static __device__ __forceinline__ void corner_acc(const float* base, int xi, int yi,
                                                  bool valid, float wgt, int lane, float4& acc) {
    if (valid) {
        float4 v = ((const float4*)(base + (size_t)(yi * 128 + xi) * NE))[lane];
        acc.x = fmaf(wgt, v.x, acc.x);
        acc.y = fmaf(wgt, v.y, acc.y);
        acc.z = fmaf(wgt, v.z, acc.z);
        acc.w = fmaf(wgt, v.w, acc.w);
    }
}

__global__ void __launch_bounds__(256) k2_sample(const float* __restrict__ kpts,
                                                 const float* __restrict__ bias,
                                                 float* __restrict__ out) {
    int gwarp = (blockIdx.x * 256 + threadIdx.x) >> 5;
    int lane = threadIdx.x & 31;
    if (gwarp >= NB * NPTS) return;
    int b = gwarp >> 12;

    float kx = kpts[(size_t)gwarp * 2 + 0];
    float ky = kpts[(size_t)gwarp * 2 + 1];
    float ix = fmaf(kx, 64.0f, 63.5f);   // (kx+1)*64 - 0.5
    float iy = fmaf(ky, 64.0f, 63.5f);
    float x0f = floorf(ix), y0f = floorf(iy);
    float wx = ix - x0f, wy = iy - y0f;
    int x0 = (int)x0f, y0 = (int)y0f, x1 = x0 + 1, y1 = y0 + 1;
    float w00 = (1.f - wx) * (1.f - wy), w10 = wx * (1.f - wy);
    float w01 = (1.f - wx) * wy,         w11 = wx * wy;

    const float* base = g_wx + (size_t)b * NPIX * NE;
    float4 acc = ((const float4*)bias)[lane];

    bool vx0 = (x0 >= 0) & (x0 < 128), vx1 = (x1 >= 0) & (x1 < 128);
    bool vy0 = (y0 >= 0) & (y0 < 128), vy1 = (y1 >= 0) & (y1 < 128);
    corner_acc(base, x0, y0, vx0 && vy0, w00, lane, acc);
    corner_acc(base, x1, y0, vx1 && vy0, w10, lane, acc);
    corner_acc(base, x0, y1, vx0 && vy1, w01, lane, acc);
    corner_acc(base, x1, y1, vx1 && vy1, w11, lane, acc);

    float ss = acc.x * acc.x + acc.y * acc.y + acc.z * acc.z + acc.w * acc.w;
#pragma unroll
    for (int m = 16; m > 0; m >>= 1) ss += __shfl_xor_sync(0xFFFFFFFFu, ss, m);
    float inv = 1.0f / fmaxf(sqrtf(ss), 1e-12f);
    acc.x *= inv; acc.y *= inv; acc.z *= inv; acc.w *= inv;
    ((float4*)(out + (size_t)gwarp * NE))[lane] = acc;
}

extern "C" void kernel_launch(void* const* d_in, const int* in_sizes, int n_in,
                              void* d_out, int out_size) {
    const float* x    = (const float*)d_in[0];
    const float* kpts = (const float*)d_in[1];
    const float* wmat = (const float*)d_in[2];
    const float* bias = (const float*)d_in[3];
    float* out = (float*)d_out;

    cudaFuncSetAttribute(k1_whiten, cudaFuncAttributeMaxDynamicSharedMemorySize, SM_TOT);
    k1_whiten<<<GRID1, 256, SM_TOT>>>(x, wmat);
    k2_sample<<<(NB * NPTS) / 8, 256>>>(kpts, bias, out);
}

// round 9
// speedup vs baseline: 1.0674x; 1.0674x over previous
#include <cuda_runtime.h>
#include <cuda_bf16.h>
#include <mma.h>
#include <cstdint>
#include <cstddef>

using namespace nvcuda;

// Shapes: x[8,256,128,128] f32, kpts[8,4096,2], W[128,256], b[128] -> out[8,4096,128] f32
#define NB 8
#define NC 256
#define NPIX 16384
#define NE 128
#define NPTS 4096
#define NTILES 1024           // NB * NPIX/128
#define GRID1 148
#define NTHR 512

// SMEM geometry (elements)
#define WLD 264               // W row stride: 256 + 8 pad (bf16), 528B (≡16 mod 128: ldmatrix conflict-free)
#define PLD 136               // X row stride: 128 + 8 pad (bf16), 272B (≡16 mod 128)
#define SM_WH_OFF 0
#define SM_WL_OFF (128 * WLD * 2)                 // 67584
#define SM_XH_OFF (2 * 128 * WLD * 2)             // 135168
#define SM_XL_OFF (SM_XH_OFF + 128 * PLD * 2)     // +34816
#define SM_TOT    (SM_XL_OFF + 128 * PLD * 2)     // 204800 B

// Scratch: Wx[b, pixel, e] fp32 (64 MiB)
__device__ float g_wx[(size_t)NB * NPIX * NE];

static __device__ __forceinline__ void split_pack(float a, float b, uint32_t& hp, uint32_t& lp) {
    __nv_bfloat16 h0 = __float2bfloat16_rn(a), h1 = __float2bfloat16_rn(b);
    float r0 = a - __bfloat162float(h0), r1 = b - __bfloat162float(h1);
    __nv_bfloat16 l0 = __float2bfloat16_rn(r0), l1 = __float2bfloat16_rn(r1);
    hp = (uint32_t)__bfloat16_as_ushort(h0) | ((uint32_t)__bfloat16_as_ushort(h1) << 16);
    lp = (uint32_t)__bfloat16_as_ushort(l0) | ((uint32_t)__bfloat16_as_ushort(l1) << 16);
}

// ===== Kernel 1: Wx[b,pix,e] = sum_c W[e,c] * x[b,c,pix]  (3x bf16-split WMMA) =====
// X kept channel-major in SMEM (conflict-free STS); consumed as col_major matrix_a.
__global__ void __launch_bounds__(NTHR, 1) k1_whiten(const float* __restrict__ x,
                                                     const float* __restrict__ wmat) {
    extern __shared__ char smem[];
    __nv_bfloat16* Wh = (__nv_bfloat16*)(smem + SM_WH_OFF);
    __nv_bfloat16* Wl = (__nv_bfloat16*)(smem + SM_WL_OFF);
    __nv_bfloat16* Xh = (__nv_bfloat16*)(smem + SM_XH_OFF);
    __nv_bfloat16* Xl = (__nv_bfloat16*)(smem + SM_XL_OFF);

    const int tid = threadIdx.x;
    const int wid = tid >> 5;
    const int wm = wid & 3;          // pixel sub-tile (32 rows)
    const int wn = wid >> 2;         // E sub-tile (32 cols)

    // ---- W prologue: [128 E][256 c] -> hi/lo bf16, row stride WLD (contiguous STS) ----
    for (int q = tid; q < 16384; q += NTHR) {
        int e = q >> 7, c2 = q & 127;
        float2 v = *(const float2*)(wmat + e * 256 + c2 * 2);
        uint32_t hp, lp; split_pack(v.x, v.y, hp, lp);
        *(uint32_t*)(Wh + e * WLD + c2 * 2) = hp;
        *(uint32_t*)(Wl + e * WLD + c2 * 2) = lp;
    }

    // staging registers: 8 float4 per thread = one 128ch x 128pix chunk per CTA
    float4 v[8];
#define LOAD_CHUNK(Tv, ck)                                                           \
    do {                                                                             \
        const float* xb_ = x + (size_t)((Tv) >> 7) * NC * NPIX + (((Tv) & 127) << 7) \
                         + (size_t)(ck) * 128 * NPIX;                                \
        _Pragma("unroll")                                                            \
        for (int j = 0; j < 8; j++) {                                                \
            int q = j * NTHR + tid;                                                  \
            v[j] = ((const float4*)(xb_ + (size_t)(q >> 5) * NPIX))[q & 31];         \
        }                                                                            \
    } while (0)

    LOAD_CHUNK(blockIdx.x, 0);
    __syncthreads();   // W tiles ready

    for (int T = blockIdx.x; T < NTILES; T += GRID1) {
        const int b = T >> 7;
        const int pix0 = (T & 127) << 7;

        wmma::fragment<wmma::accumulator, 16, 16, 16, float> acc[2][2];
#pragma unroll
        for (int mi = 0; mi < 2; mi++)
#pragma unroll
            for (int ni = 0; ni < 2; ni++)
                wmma::fill_fragment(acc[mi][ni], 0.0f);

        for (int chunk = 0; chunk < 2; chunk++) {
            // ---- STS staged chunk: channel-major, contiguous 8B stores ----
#pragma unroll
            for (int j = 0; j < 8; j++) {
                int q = j * NTHR + tid;
                int ch = q >> 5, p4 = q & 31;
                float4 t = v[j];
                uint32_t h0, l0, h1, l1;
                split_pack(t.x, t.y, h0, l0);
                split_pack(t.z, t.w, h1, l1);
                int off = ch * PLD + p4 * 4;
                *(uint2*)(Xh + off) = make_uint2(h0, h1);
                *(uint2*)(Xl + off) = make_uint2(l0, l1);
            }
            __syncthreads();

            // ---- prefetch next chunk into regs (overlaps with MMA below) ----
            {
                int nT = (chunk == 0) ? T : T + GRID1;
                int nck = chunk ^ 1;
                if (nT < NTILES) LOAD_CHUNK(nT, nck);
            }

            // ---- MMA over this chunk (K = 128 local channels) ----
#pragma unroll
            for (int ks = 0; ks < 8; ks++) {
                const int kb = ks * 16;                // local channel offset
                const int kg = chunk * 128 + kb;       // global (for W)
                wmma::fragment<wmma::matrix_a, 16, 16, 16, __nv_bfloat16, wmma::col_major> ah[2], al[2];
#pragma unroll
                for (int mi = 0; mi < 2; mi++) {
                    int prow = wm * 32 + mi * 16;
                    wmma::load_matrix_sync(ah[mi], Xh + kb * PLD + prow, PLD);
                    wmma::load_matrix_sync(al[mi], Xl + kb * PLD + prow, PLD);
                }
#pragma unroll
                for (int ni = 0; ni < 2; ni++) {
                    int erow = wn * 32 + ni * 16;
                    wmma::fragment<wmma::matrix_b, 16, 16, 16, __nv_bfloat16, wmma::col_major> bh, bl;
                    wmma::load_matrix_sync(bh, Wh + erow * WLD + kg, WLD);
                    wmma::load_matrix_sync(bl, Wl + erow * WLD + kg, WLD);
#pragma unroll
                    for (int mi = 0; mi < 2; mi++) {
                        wmma::mma_sync(acc[mi][ni], ah[mi], bh, acc[mi][ni]);
                        wmma::mma_sync(acc[mi][ni], al[mi], bh, acc[mi][ni]);
                        wmma::mma_sync(acc[mi][ni], ah[mi], bl, acc[mi][ni]);
                    }
                }
            }
            __syncthreads();   // MMAs done before X overwrite next chunk
        }

        // ---- epilogue: acc -> g_wx[b, pix, e] (E-contiguous) ----
        float* gp = g_wx + ((size_t)(b * NPIX + pix0)) * NE;
#pragma unroll
        for (int mi = 0; mi < 2; mi++)
#pragma unroll
            for (int ni = 0; ni < 2; ni++)
                wmma::store_matrix_sync(gp + (size_t)(wm * 32 + mi * 16) * NE + wn * 32 + ni * 16,
                                        acc[mi][ni], NE, wmma::mem_row_major);
    }
#undef LOAD_CHUNK
}

// ===== Kernel 2: bilinear gather on Wx + bias + L2-normalize =====
static __device__ __forceinline__ void corner_acc(const float* base, int xi, int yi,
                                                  bool valid, float wgt, int lane, float4& acc) {
    if (valid) {
        float4 vv = ((const float4*)(base + (size_t)(yi * 128 + xi) * NE))[lane];
        acc.x = fmaf(wgt, vv.x, acc.x);
        acc.y = fmaf(wgt, vv.y, acc.y);
        acc.z = fmaf(wgt, vv.z, acc.z);
        acc.w = fmaf(wgt, vv.w, acc.w);
    }
}

__global__ void __launch_bounds__(256) k2_sample(const float* __restrict__ kpts,
                                                 const float* __restrict__ bias,
                                                 float* __restrict__ out) {
    int gwarp = (blockIdx.x * 256 + threadIdx.x) >> 5;
    int lane = threadIdx.x & 31;
    if (gwarp >= NB * NPTS) return;
    int b = gwarp >> 12;

    float2 kp = ((const float2*)kpts)[gwarp];
    float ix = fmaf(kp.x, 64.0f, 63.5f);   // (kx+1)*64 - 0.5
    float iy = fmaf(kp.y, 64.0f, 63.5f);
    float x0f = floorf(ix), y0f = floorf(iy);
    float wx = ix - x0f, wy = iy - y0f;
    int x0 = (int)x0f, y0 = (int)y0f, x1 = x0 + 1, y1 = y0 + 1;
    float w00 = (1.f - wx) * (1.f - wy), w10 = wx * (1.f - wy);
    float w01 = (1.f - wx) * wy,         w11 = wx * wy;

    const float* base = g_wx + (size_t)b * NPIX * NE;
    float4 acc = ((const float4*)bias)[lane];

    bool vx0 = (x0 >= 0) & (x0 < 128), vx1 = (x1 >= 0) & (x1 < 128);
    bool vy0 = (y0 >= 0) & (y0 < 128), vy1 = (y1 >= 0) & (y1 < 128);
    corner_acc(base, x0, y0, vx0 && vy0, w00, lane, acc);
    corner_acc(base, x1, y0, vx1 && vy0, w10, lane, acc);
    corner_acc(base, x0, y1, vx0 && vy1, w01, lane, acc);
    corner_acc(base, x1, y1, vx1 && vy1, w11, lane, acc);

    float ss = acc.x * acc.x + acc.y * acc.y + acc.z * acc.z + acc.w * acc.w;
#pragma unroll
    for (int m = 16; m > 0; m >>= 1) ss += __shfl_xor_sync(0xFFFFFFFFu, ss, m);
    float inv = 1.0f / fmaxf(sqrtf(ss), 1e-12f);
    acc.x *= inv; acc.y *= inv; acc.z *= inv; acc.w *= inv;
    ((float4*)(out + (size_t)gwarp * NE))[lane] = acc;
}

extern "C" void kernel_launch(void* const* d_in, const int* in_sizes, int n_in,
                              void* d_out, int out_size) {
    const float* x    = (const float*)d_in[0];
    const float* kpts = (const float*)d_in[1];
    const float* wmat = (const float*)d_in[2];
    const float* bias = (const float*)d_in[3];
    float* out = (float*)d_out;

    cudaFuncSetAttribute(k1_whiten, cudaFuncAttributeMaxDynamicSharedMemorySize, SM_TOT);
    k1_whiten<<<GRID1, NTHR, SM_TOT>>>(x, wmat);
    k2_sample<<<(NB * NPTS) / 8, 256>>>(kpts, bias, out);
}